// round 13
// baseline (speedup 1.0000x reference)
#include <cuda_runtime.h>
#include <cuda_fp16.h>
#include <cstdint>

#define BN 8192
#define CN 16
#define DN 256
#define RN 64
#define EN 32
#define ORDN 16
#define LN 32

#define MT 128   // bodies per CTA
#define NH 128   // j-half per CTA
#define KC 32    // K chunk (two k16 mma tiles)

// Scratch (__device__ globals; every element written each launch)
__device__ float g_q2[BN * CN * 2];
__device__ int   g_cnt[BN / MT];   // zero-init at load; reset by last CTA each launch

// smem u32 layout during GEMM (first 33280 B):
//  Dhi [0,2048)  Dlo [2048,4096)        8 KB each
//  Bhi [4096,6208)  Blo [6208,8320)     8448 B each (33-u32-pair padded rows)
// Tail reuse: acs [0,256) bcs [256,768) bss [768,784) ps [1024,9216) u32
#define SM_DLO 2048
#define SM_BHI 4096
#define SM_BLO 6208
#define SM_U32 9216   // 36864 B dynamic smem

__device__ __forceinline__ uint32_t pk_h2(float a, float b) {
    __half2 h = __floats2half2_rn(a, b);  // .x = low half = first arg
    return *reinterpret_cast<uint32_t*>(&h);
}

// mma m16n8k16 fp16 -> fp32 accum (sm_80+ baseline; valid on plain sm_100)
__device__ __forceinline__ void mma_f16(float* c, uint4 a, uint2 b) {
    asm volatile(
        "mma.sync.aligned.m16n8k16.row.col.f32.f16.f16.f32 "
        "{%0,%1,%2,%3}, {%4,%5,%6,%7}, {%8,%9}, {%0,%1,%2,%3};"
        : "+f"(c[0]), "+f"(c[1]), "+f"(c[2]), "+f"(c[3])
        : "r"(a.x), "r"(a.y), "r"(a.z), "r"(a.w), "r"(b.x), "r"(b.y));
}

// ---------------------------------------------------------------------------
// quad_mma_kernel: fp16x3 GEMM quad-form + fused ARX tail.
// grid (BN/MT, 2, CN), 256 thr, 2 CTAs/SM.
// Phase 1 (all CTAs): q[b,c,half] = sum_{j in half} (sum_i sig*(mu-z))^2
// Phase 2 (last CTA per btile): softmax + ARX recursion + weighted output
//         for this btile's 128 bodies (threadFenceReduction pattern).
// ---------------------------------------------------------------------------
__global__ __launch_bounds__(256, 2) void quad_mma_kernel(
    const float* __restrict__ z, const float* __restrict__ mu,
    const float* __restrict__ sig, const float* __restrict__ y,
    const float* __restrict__ u, const float* __restrict__ a_coef,
    const float* __restrict__ b_coef, const float* __restrict__ bias,
    float* __restrict__ out) {
    extern __shared__ uint32_t smu[];
    const int btile = blockIdx.x, nh = blockIdx.y, c = blockIdx.z;
    const int b0 = btile * MT, j0 = nh * NH;
    const int tid = threadIdx.x, wid = tid >> 5, lane = tid & 31;

    float acc[16][4];
#pragma unroll
    for (int nt = 0; nt < 16; nt++)
#pragma unroll
        for (int i = 0; i < 4; i++) acc[nt][i] = 0.f;

    const float* sigc = sig + (size_t)c * DN * DN;
    __half* BhiH = (__half*)(smu + SM_BHI);
    __half* BloH = (__half*)(smu + SM_BLO);

    for (int kt = 0; kt < DN / KC; kt++) {
        const int i0 = kt * KC;
        if (kt) __syncthreads();

        // --- stage D (A operand): d = mu - z, fp16 hi/lo, fragment order ---
#pragma unroll
        for (int it = 0; it < 4; it++) {
            int idx = tid + it * 256;
            int b = idx >> 3, i4 = idx & 7;
            float4 zv = *(const float4*)(z + (size_t)(b0 + b) * DN + i0 + i4 * 4);
            float4 m4 = *(const float4*)(mu + c * DN + i0 + i4 * 4);
            float v[4] = {m4.x - zv.x, m4.y - zv.y, m4.z - zv.z, m4.w - zv.w};
            __half h0 = __float2half_rn(v[0]), h1 = __float2half_rn(v[1]);
            __half h2 = __float2half_rn(v[2]), h3 = __float2half_rn(v[3]);
            float l0 = v[0] - __half2float(h0), l1 = v[1] - __half2float(h1);
            float l2 = v[2] - __half2float(h2), l3 = v[3] - __half2float(h3);
            int r = b & 15, g = r & 7, rh = r >> 3, mslot = b >> 4;
            int kt16 = i4 >> 2, sl = (i4 >> 1) & 1, t0 = (i4 & 1) * 2;
            int reg = rh + 2 * sl;
            int base = ((mslot * 2 + kt16) * 32 + g * 4 + t0) * 4 + reg;
            smu[base]              = pk_h2(__half2float(h0), __half2float(h1));
            smu[base + 4]          = pk_h2(__half2float(h2), __half2float(h3));
            smu[SM_DLO + base]     = pk_h2(l0, l1);
            smu[SM_DLO + base + 4] = pk_h2(l2, l3);
        }
        // --- stage B: sig K-major (k=i, n=j), fp16 hi/lo, padded rows (33) ---
#pragma unroll
        for (int it = 0; it < 4; it++) {
            int idx = tid + it * 256;
            int ii = idx >> 5, j4 = idx & 31;
            float4 av = *(const float4*)(sigc + (size_t)(i0 + ii) * DN + j0 + j4 * 4);
            float v[4] = {av.x, av.y, av.z, av.w};
            int kk = ii & 15, kt16 = ii >> 4;
            int t = (kk & 7) >> 1, sl = kk >> 3, hp = kk & 1;
#pragma unroll
            for (int e = 0; e < 4; e++) {
                int jl = j4 * 4 + e;
                int nt = jl >> 3, g = jl & 7;
                int hidx = ((((kt16 * 16 + nt) * 33 + g * 4 + t) * 2 + sl) * 2) + hp;
                __half h = __float2half_rn(v[e]);
                BhiH[hidx] = h;
                BloH[hidx] = __float2half_rn(v[e] - __half2float(h));
            }
        }
        __syncthreads();

        // --- compute: 2 k16-tiles x 16 ntiles x {hh, hl, lh} ---
        const uint4* Dhi4 = (const uint4*)smu;
        const uint4* Dlo4 = (const uint4*)(smu + SM_DLO);
        const uint2* Bhi2 = (const uint2*)(smu + SM_BHI);
        const uint2* Blo2 = (const uint2*)(smu + SM_BLO);
#pragma unroll
        for (int ktile = 0; ktile < 2; ktile++) {
            uint4 ah = Dhi4[(wid * 2 + ktile) * 32 + lane];
            uint4 al = Dlo4[(wid * 2 + ktile) * 32 + lane];
#pragma unroll
            for (int nt = 0; nt < 16; nt++) {
                uint2 bh = Bhi2[(ktile * 16 + nt) * 33 + lane];
                uint2 bl = Blo2[(ktile * 16 + nt) * 33 + lane];
                mma_f16(acc[nt], ah, bh);
                mma_f16(acc[nt], ah, bl);
                mma_f16(acc[nt], al, bh);
            }
        }
    }

    // Epilogue: q = sum_j acc^2 over this j-half -> g_q2.
    float q0 = 0.f, q1 = 0.f;
#pragma unroll
    for (int nt = 0; nt < 16; nt++) {
        q0 += acc[nt][0] * acc[nt][0] + acc[nt][1] * acc[nt][1];
        q1 += acc[nt][2] * acc[nt][2] + acc[nt][3] * acc[nt][3];
    }
    q0 += __shfl_xor_sync(0xffffffffu, q0, 1);
    q0 += __shfl_xor_sync(0xffffffffu, q0, 2);
    q1 += __shfl_xor_sync(0xffffffffu, q1, 1);
    q1 += __shfl_xor_sync(0xffffffffu, q1, 2);
    if ((lane & 3) == 0) {
        int b = b0 + wid * 16 + (lane >> 2);
        g_q2[((size_t)b * CN + c) * 2 + nh]       = q0;
        g_q2[((size_t)(b + 8) * CN + c) * 2 + nh] = q1;
    }

    // --- last-CTA detection (threadFenceReduction pattern) ---
    __threadfence();
    __syncthreads();
    __shared__ int lastFlag;
    if (tid == 0) {
        int old = atomicAdd(&g_cnt[btile], 1);
        lastFlag = (old == 31);
        if (old == 31) g_cnt[btile] = 0;   // reset for next launch/replay
    }
    __syncthreads();
    if (!lastFlag) return;
    __threadfence();

    // ================= fused ARX tail: this btile's 128 bodies ==============
    float* acs = (float*)smu;           // [256] a_coef
    float* bcs = (float*)smu + 256;     // [512] b_coef
    float* bss = (float*)smu + 768;     // [16]  bias
    float* ps  = (float*)(smu + 1024);  // [16*16*32] XOR-swizzled psi*pred
    acs[tid] = a_coef[tid];
    bcs[tid] = b_coef[tid];
    bcs[tid + 256] = b_coef[tid + 256];
    if (tid < CN) bss[tid] = bias[tid];
    __syncthreads();

    const int tb = tid >> 4;     // body-in-group 0..15
    const int tc = tid & 15;     // class 0..15 (16-lane shfl group)

    for (int k = 0; k < 8; k++) {
        const int b = b0 + k * 16 + tb;

        float d2 = __ldcg(&g_q2[((size_t)b * CN + tc) * 2]) +
                   __ldcg(&g_q2[((size_t)b * CN + tc) * 2 + 1]);
        d2 = fmaxf(d2, 1e-8f);

        float mn = d2;
#pragma unroll
        for (int m = 8; m; m >>= 1) mn = fminf(mn, __shfl_xor_sync(0xffffffffu, mn, m));
        float e = expf(-(d2 - mn));
        float ssum = e;
#pragma unroll
        for (int m = 8; m; m >>= 1) ssum += __shfl_xor_sync(0xffffffffu, ssum, m);
        float psi = e / ssum;

        const float4* uv = (const float4*)(u + ((size_t)b * CN + tc) * EN);
        float ub = bss[tc];
#pragma unroll
        for (int kk = 0; kk < EN / 4; kk++) {
            float4 uu = uv[kk];
            const float* bc = &bcs[tc * EN + kk * 4];
            ub += uu.x * bc[0] + uu.y * bc[1] + uu.z * bc[2] + uu.w * bc[3];
        }

        float s[ORDN];
        const float4* yv = (const float4*)(y + ((size_t)b * CN + tc) * RN + (RN - ORDN));
#pragma unroll
        for (int kk = 0; kk < ORDN / 4; kk++) {
            float4 t = yv[kk];
            s[kk * 4 + 0] = t.x; s[kk * 4 + 1] = t.y;
            s[kk * 4 + 2] = t.z; s[kk * 4 + 3] = t.w;
        }
        float ar[ORDN];
#pragma unroll
        for (int o = 0; o < ORDN; o++) ar[o] = acs[tc * ORDN + o];

        float* myps = &ps[(tb * 16 + tc) * 32];
#pragma unroll
        for (int l = 0; l < LN; l++) {
            float y0 = 0.f, y1 = 0.f;
#pragma unroll
            for (int o = 0; o < ORDN; o += 2) {
                y0 += s[o] * ar[o];
                y1 += s[o + 1] * ar[o + 1];
            }
            float yn = ub + y0 + y1;
#pragma unroll
            for (int o = 0; o < ORDN - 1; o++) s[o] = s[o + 1];
            s[ORDN - 1] = yn;
            myps[l ^ tc] = psi * yn;   // XOR swizzle -> conflict-free c-sum
        }
        __syncthreads();

        // out[b, l] = sum_c psi_c * pred_{c,l}
#pragma unroll
        for (int p = tid; p < 16 * LN; p += 256) {
            int bb = p >> 5, l = p & 31;
            float a = 0.f;
#pragma unroll
            for (int cc = 0; cc < CN; cc++) a += ps[(bb * 16 + cc) * 32 + (l ^ cc)];
            out[(size_t)(b0 + k * 16 + bb) * LN + l] = a;
        }
        __syncthreads();
    }
}

// ---------------------------------------------------------------------------
extern "C" void kernel_launch(void* const* d_in, const int* in_sizes, int n_in,
                              void* d_out, int out_size) {
    const float* y      = (const float*)d_in[0];
    const float* z      = (const float*)d_in[1];
    const float* u      = (const float*)d_in[2];
    const float* mu     = (const float*)d_in[3];
    const float* sig    = (const float*)d_in[4];
    const float* a_coef = (const float*)d_in[5];
    const float* b_coef = (const float*)d_in[6];
    const float* bias   = (const float*)d_in[7];
    float* out = (float*)d_out;

    const int qsmem = SM_U32 * sizeof(uint32_t);  // 36864 B
    cudaFuncSetAttribute(quad_mma_kernel,
                         cudaFuncAttributeMaxDynamicSharedMemorySize, qsmem);

    quad_mma_kernel<<<dim3(BN / MT, 2, CN), 256, qsmem>>>(
        z, mu, sig, y, u, a_coef, b_coef, bias, out);
}

// round 14
// speedup vs baseline: 1.2495x; 1.2495x over previous
#include <cuda_runtime.h>
#include <cuda_fp16.h>
#include <cstdint>

#define BN 8192
#define CN 16
#define DN 256
#define RN 64
#define EN 32
#define ORDN 16
#define LN 32

#define MT 128   // bodies per CTA
#define NH 128   // j-half per CTA
#define KC 32    // K chunk (two k16 mma tiles)

// Scratch: 4 partials per (b,c): [b][c][nh*2 + ngroup]; all written each launch
__device__ float g_q4[BN * CN * 4];

// smem u32 layout (per CTA, 33280 B):
//  Dhi [0,2048)  Dlo [2048,4096)        8 KB each
//  Bhi [4096,6208)  Blo [6208,8320)     8448 B each (33-u32-pair padded rows)
#define SM_DLO 2048
#define SM_BHI 4096
#define SM_BLO 6208
#define SM_U32 8320

__device__ __forceinline__ uint32_t pk_h2(float a, float b) {
    __half2 h = __floats2half2_rn(a, b);  // .x = low half = first arg
    return *reinterpret_cast<uint32_t*>(&h);
}

// mma m16n8k16 fp16 -> fp32 accum (sm_80+ baseline; valid on plain sm_100)
__device__ __forceinline__ void mma_f16(float* c, uint4 a, uint2 b) {
    asm volatile(
        "mma.sync.aligned.m16n8k16.row.col.f32.f16.f16.f32 "
        "{%0,%1,%2,%3}, {%4,%5,%6,%7}, {%8,%9}, {%0,%1,%2,%3};"
        : "+f"(c[0]), "+f"(c[1]), "+f"(c[2]), "+f"(c[3])
        : "r"(a.x), "r"(a.y), "r"(a.z), "r"(a.w), "r"(b.x), "r"(b.y));
}

// ---------------------------------------------------------------------------
// quad_mma_kernel: q-partials of d2 over one j-half:
//   q[b,c,half,ng] = sum_{j in ng-quarter} ( sum_i sig[c,i,j]*(mu[c,i]-z[b,i]) )^2
// fp16x3 split (hh + hl + lh) on mma.sync m16n8k16.
// grid (BN/MT, 2, CN), 256 thr, 2 CTAs/SM.
// Warp tile M32 x N64: warp w -> m16-slots {2*(w&3), +1}, ntiles {8*(w>>2)..+7}
// => per-warp LDS per k16: A 2KB + B 4KB (was 1+8) -> 1.5x less smem traffic.
// ---------------------------------------------------------------------------
__global__ __launch_bounds__(256, 2) void quad_mma_kernel(
    const float* __restrict__ z, const float* __restrict__ mu,
    const float* __restrict__ sig) {
    extern __shared__ uint32_t smu[];
    const int btile = blockIdx.x, nh = blockIdx.y, c = blockIdx.z;
    const int b0 = btile * MT, j0 = nh * NH;
    const int tid = threadIdx.x, wid = tid >> 5, lane = tid & 31;
    const int ms = (wid & 3) * 2;   // base m16 slot (covers 32 body rows)
    const int ng = wid >> 2;        // n-group: ntiles 8*ng .. 8*ng+7

    float acc[2][8][4];
#pragma unroll
    for (int sub = 0; sub < 2; sub++)
#pragma unroll
        for (int nt = 0; nt < 8; nt++)
#pragma unroll
            for (int i = 0; i < 4; i++) acc[sub][nt][i] = 0.f;

    const float* sigc = sig + (size_t)c * DN * DN;
    __half* BhiH = (__half*)(smu + SM_BHI);
    __half* BloH = (__half*)(smu + SM_BLO);

    for (int kt = 0; kt < DN / KC; kt++) {
        const int i0 = kt * KC;
        if (kt) __syncthreads();  // previous chunk's reads complete

        // --- stage D (A operand): d = mu - z, fp16 hi/lo, fragment order ---
#pragma unroll
        for (int it = 0; it < 4; it++) {
            int idx = tid + it * 256;          // 0..1023
            int b = idx >> 3, i4 = idx & 7;
            float4 zv = *(const float4*)(z + (size_t)(b0 + b) * DN + i0 + i4 * 4);
            float4 m4 = *(const float4*)(mu + c * DN + i0 + i4 * 4);  // warp-uniform
            float v[4] = {m4.x - zv.x, m4.y - zv.y, m4.z - zv.z, m4.w - zv.w};
            __half h0 = __float2half_rn(v[0]), h1 = __float2half_rn(v[1]);
            __half h2 = __float2half_rn(v[2]), h3 = __float2half_rn(v[3]);
            float l0 = v[0] - __half2float(h0), l1 = v[1] - __half2float(h1);
            float l2 = v[2] - __half2float(h2), l3 = v[3] - __half2float(h3);
            int r = b & 15, g = r & 7, rh = r >> 3, mslot = b >> 4;
            int kt16 = i4 >> 2;
            int sl = (i4 >> 1) & 1;
            int t0 = (i4 & 1) * 2;
            int reg = rh + 2 * sl;
            int base = ((mslot * 2 + kt16) * 32 + g * 4 + t0) * 4 + reg;
            smu[base]              = pk_h2(__half2float(h0), __half2float(h1));
            smu[base + 4]          = pk_h2(__half2float(h2), __half2float(h3));
            smu[SM_DLO + base]     = pk_h2(l0, l1);
            smu[SM_DLO + base + 4] = pk_h2(l2, l3);
        }
        // --- stage B: sig K-major (k=i, n=j), fp16 hi/lo, padded rows (33) ---
#pragma unroll
        for (int it = 0; it < 4; it++) {
            int idx = tid + it * 256;          // 0..1023
            int ii = idx >> 5, j4 = idx & 31;  // coalesced 512B per warp
            float4 av = *(const float4*)(sigc + (size_t)(i0 + ii) * DN + j0 + j4 * 4);
            float v[4] = {av.x, av.y, av.z, av.w};
            int kk = ii & 15, kt16 = ii >> 4;
            int t = (kk & 7) >> 1, sl = kk >> 3, hp = kk & 1;
#pragma unroll
            for (int e = 0; e < 4; e++) {
                int jl = j4 * 4 + e;
                int nt = jl >> 3, g = jl & 7;
                int hidx = ((((kt16 * 16 + nt) * 33 + g * 4 + t) * 2 + sl) * 2) + hp;
                __half h = __float2half_rn(v[e]);
                BhiH[hidx] = h;
                BloH[hidx] = __float2half_rn(v[e] - __half2float(h));
            }
        }
        __syncthreads();

        // --- compute: 2 k16-tiles x (2 m-subs x 8 ntiles) x {hh, hl, lh} ---
        const uint4* Dhi4 = (const uint4*)smu;
        const uint4* Dlo4 = (const uint4*)(smu + SM_DLO);
        const uint2* Bhi2 = (const uint2*)(smu + SM_BHI);
        const uint2* Blo2 = (const uint2*)(smu + SM_BLO);
#pragma unroll
        for (int ktile = 0; ktile < 2; ktile++) {
            uint4 ah0 = Dhi4[((ms + 0) * 2 + ktile) * 32 + lane];
            uint4 al0 = Dlo4[((ms + 0) * 2 + ktile) * 32 + lane];
            uint4 ah1 = Dhi4[((ms + 1) * 2 + ktile) * 32 + lane];
            uint4 al1 = Dlo4[((ms + 1) * 2 + ktile) * 32 + lane];
#pragma unroll
            for (int nt = 0; nt < 8; nt++) {
                const int ntg = ng * 8 + nt;
                uint2 bh = Bhi2[(ktile * 16 + ntg) * 33 + lane];
                uint2 bl = Blo2[(ktile * 16 + ntg) * 33 + lane];
                mma_f16(acc[0][nt], ah0, bh);
                mma_f16(acc[0][nt], ah0, bl);
                mma_f16(acc[0][nt], al0, bh);
                mma_f16(acc[1][nt], ah1, bh);
                mma_f16(acc[1][nt], ah1, bl);
                mma_f16(acc[1][nt], al1, bh);
            }
        }
    }

    // Epilogue: per m-sub, q = sum_j acc^2 over this warp's n-quarter.
#pragma unroll
    for (int sub = 0; sub < 2; sub++) {
        float q0 = 0.f, q1 = 0.f;
#pragma unroll
        for (int nt = 0; nt < 8; nt++) {
            q0 += acc[sub][nt][0] * acc[sub][nt][0] + acc[sub][nt][1] * acc[sub][nt][1];
            q1 += acc[sub][nt][2] * acc[sub][nt][2] + acc[sub][nt][3] * acc[sub][nt][3];
        }
        q0 += __shfl_xor_sync(0xffffffffu, q0, 1);
        q0 += __shfl_xor_sync(0xffffffffu, q0, 2);
        q1 += __shfl_xor_sync(0xffffffffu, q1, 1);
        q1 += __shfl_xor_sync(0xffffffffu, q1, 2);
        if ((lane & 3) == 0) {
            int b = b0 + (ms + sub) * 16 + (lane >> 2);
            g_q4[(((size_t)b * CN + c) * 2 + nh) * 2 + ng]       = q0;
            g_q4[(((size_t)(b + 8) * CN + c) * 2 + nh) * 2 + ng] = q1;
        }
    }
}

// ---------------------------------------------------------------------------
// Kernel B: d2 -> softmax -> ARX recursion -> weighted output.
// ---------------------------------------------------------------------------
__global__ __launch_bounds__(256) void arx_out_kernel(
    const float* __restrict__ y, const float* __restrict__ u,
    const float* __restrict__ a_coef, const float* __restrict__ b_coef,
    const float* __restrict__ bias, float* __restrict__ out) {
    __shared__ float ps[16 * 16 * 33];
    __shared__ float acs[CN * ORDN];
    __shared__ float bcs[CN * EN];
    __shared__ float bss[CN];

    const int tid = threadIdx.x;
    if (tid < CN * ORDN) acs[tid] = a_coef[tid];
    for (int i = tid; i < CN * EN; i += 256) bcs[i] = b_coef[i];
    if (tid < CN) bss[tid] = bias[tid];
    __syncthreads();

    const int tb = tid >> 4;
    const int tc = tid & 15;
    const int b  = blockIdx.x * 16 + tb;

    const float4 qv = *(const float4*)&g_q4[((size_t)b * CN + tc) * 4];
    float d2 = fmaxf((qv.x + qv.y) + (qv.z + qv.w), 1e-8f);

    float mn = d2;
#pragma unroll
    for (int m = 8; m; m >>= 1) mn = fminf(mn, __shfl_xor_sync(0xffffffffu, mn, m));
    float e = expf(-(d2 - mn));
    float ssum = e;
#pragma unroll
    for (int m = 8; m; m >>= 1) ssum += __shfl_xor_sync(0xffffffffu, ssum, m);
    float psi = e / ssum;

    const float4* uv = (const float4*)(u + ((size_t)b * CN + tc) * EN);
    float ub = bss[tc];
#pragma unroll
    for (int k = 0; k < EN / 4; k++) {
        float4 uu = uv[k];
        const float* bc = &bcs[tc * EN + k * 4];
        ub += uu.x * bc[0] + uu.y * bc[1] + uu.z * bc[2] + uu.w * bc[3];
    }

    float s[ORDN];
    const float4* yv = (const float4*)(y + ((size_t)b * CN + tc) * RN + (RN - ORDN));
#pragma unroll
    for (int k = 0; k < ORDN / 4; k++) {
        float4 t = yv[k];
        s[k * 4 + 0] = t.x; s[k * 4 + 1] = t.y;
        s[k * 4 + 2] = t.z; s[k * 4 + 3] = t.w;
    }
    float ar[ORDN];
#pragma unroll
    for (int o = 0; o < ORDN; o++) ar[o] = acs[tc * ORDN + o];

    float* myps = &ps[(tb * 16 + tc) * 33];
#pragma unroll
    for (int l = 0; l < LN; l++) {
        float y0 = 0.f, y1 = 0.f;
#pragma unroll
        for (int o = 0; o < ORDN; o += 2) {
            y0 += s[o] * ar[o];
            y1 += s[o + 1] * ar[o + 1];
        }
        float yn = ub + y0 + y1;
#pragma unroll
        for (int o = 0; o < ORDN - 1; o++) s[o] = s[o + 1];
        s[ORDN - 1] = yn;
        myps[l] = psi * yn;
    }
    __syncthreads();

    for (int o = tid; o < 16 * LN; o += 256) {
        int bb = o >> 5, l = o & 31;
        float acc = 0.f;
#pragma unroll
        for (int cc = 0; cc < CN; cc++) acc += ps[(bb * 16 + cc) * 33 + l];
        out[(size_t)(blockIdx.x * 16 + bb) * LN + l] = acc;
    }
}

// ---------------------------------------------------------------------------
extern "C" void kernel_launch(void* const* d_in, const int* in_sizes, int n_in,
                              void* d_out, int out_size) {
    const float* y      = (const float*)d_in[0];
    const float* z      = (const float*)d_in[1];
    const float* u      = (const float*)d_in[2];
    const float* mu     = (const float*)d_in[3];
    const float* sig    = (const float*)d_in[4];
    const float* a_coef = (const float*)d_in[5];
    const float* b_coef = (const float*)d_in[6];
    const float* bias   = (const float*)d_in[7];
    float* out = (float*)d_out;

    const int qsmem = SM_U32 * sizeof(uint32_t);  // 33280 B
    cudaFuncSetAttribute(quad_mma_kernel,
                         cudaFuncAttributeMaxDynamicSharedMemorySize, qsmem);

    quad_mma_kernel<<<dim3(BN / MT, 2, CN), 256, qsmem>>>(z, mu, sig);
    arx_out_kernel<<<BN / 16, 256>>>(y, u, a_coef, b_coef, bias, out);
}